// round 1
// baseline (speedup 1.0000x reference)
#include <cuda_runtime.h>
#include <cuda_bf16.h>
#include <math.h>

// Problem dims (fixed by setup_inputs)
#define B_    4
#define L_    4096
#define H_    16
#define NB_   64
#define D_    1024
#define HID_  128
#define NS_   1024            // H_*NB_
#define M_    16384           // B_*L_
#define NCH_  16              // chunks per channel
#define TCH_  256             // timesteps per chunk (NCH_*TCH_ == L_)
#define PI_F  3.14159265358979323846f

// ---------------- scratch (device globals; no allocations allowed) ----------
__device__ float g_Hbuf [M_ * 256];        // gelu(X@W1+b1) for both MLPs, (m, 256)
__device__ float g_alpha[(size_t)M_ * NS_]; // 64 MB
__device__ float g_u    [(size_t)M_ * NS_]; // 64 MB
__device__ float g_cA   [B_ * NS_ * NCH_];
__device__ float g_cU   [B_ * NS_ * NCH_];
__device__ float g_carry[B_ * NS_ * NCH_];

__device__ __forceinline__ float gelu_exact(float v) {
    return 0.5f * v * (1.0f + erff(v * 0.70710678118654752440f));
}

// ============================================================================
// Kernel 1: H = gelu(X @ [Wr1 | Wm1] + [br1 | bm1])
// M=16384, N=256, K=1024.  BM=128, BN=64, BK=16, 256 threads, TM=8, TN=4.
// ============================================================================
__global__ __launch_bounds__(256) void k_gemm1(
    const float* __restrict__ X,
    const float* __restrict__ Wr1, const float* __restrict__ br1,
    const float* __restrict__ Wm1, const float* __restrict__ bm1)
{
    const int bn0 = blockIdx.x * 64;       // 0,64,128,192
    const int bm0 = blockIdx.y * 128;
    const float* W    = (bn0 < 128) ? Wr1 : Wm1;
    const float* bias = (bn0 < 128) ? br1 : bm1;
    const int wcol0 = bn0 & 127;

    __shared__ float As[16][128];
    __shared__ float Bs[16][64];

    const int tid = threadIdx.x;
    const int tx = tid & 15;   // n group (4 cols)
    const int ty = tid >> 4;   // m group (8 rows)

    float acc[8][4];
    #pragma unroll
    for (int i = 0; i < 8; i++)
        #pragma unroll
        for (int j = 0; j < 4; j++) acc[i][j] = 0.f;

    for (int k0 = 0; k0 < D_; k0 += 16) {
        // A tile: 128x16 -> 512 float4, 2 per thread (store transposed)
        #pragma unroll
        for (int i = 0; i < 2; i++) {
            int f   = tid + i * 256;
            int row = f >> 2;
            int c4  = (f & 3) * 4;
            float4 v = *reinterpret_cast<const float4*>(
                &X[(size_t)(bm0 + row) * D_ + k0 + c4]);
            As[c4 + 0][row] = v.x; As[c4 + 1][row] = v.y;
            As[c4 + 2][row] = v.z; As[c4 + 3][row] = v.w;
        }
        // B tile: 16x64 -> 256 float4, 1 per thread
        {
            int row = tid >> 4;
            int c4  = (tid & 15) * 4;
            float4 v = *reinterpret_cast<const float4*>(
                &W[(size_t)(k0 + row) * HID_ + wcol0 + c4]);
            *reinterpret_cast<float4*>(&Bs[row][c4]) = v;
        }
        __syncthreads();
        #pragma unroll
        for (int k = 0; k < 16; k++) {
            float a[8], b[4];
            float4 a0 = *reinterpret_cast<const float4*>(&As[k][ty * 8]);
            float4 a1 = *reinterpret_cast<const float4*>(&As[k][ty * 8 + 4]);
            a[0]=a0.x; a[1]=a0.y; a[2]=a0.z; a[3]=a0.w;
            a[4]=a1.x; a[5]=a1.y; a[6]=a1.z; a[7]=a1.w;
            float4 bb = *reinterpret_cast<const float4*>(&Bs[k][tx * 4]);
            b[0]=bb.x; b[1]=bb.y; b[2]=bb.z; b[3]=bb.w;
            #pragma unroll
            for (int i = 0; i < 8; i++)
                #pragma unroll
                for (int j = 0; j < 4; j++)
                    acc[i][j] = fmaf(a[i], b[j], acc[i][j]);
        }
        __syncthreads();
    }

    #pragma unroll
    for (int j = 0; j < 4; j++) {
        float bj = bias[wcol0 + tx * 4 + j];
        #pragma unroll
        for (int i = 0; i < 8; i++) {
            int m = bm0 + ty * 8 + i;
            float v = acc[i][j] + bj;
            g_Hbuf[(size_t)m * 256 + bn0 + tx * 4 + j] = gelu_exact(v);
        }
    }
}

// ============================================================================
// Kernel 2: both second GEMMs (K=128) + full per-element epilogue.
// BM=64, BN=64, BK=32, 256 threads, TM=4, TN=4, dual accumulators (r & m).
// Writes R, K to d_out regions; alpha,u to scratch.
// ============================================================================
__global__ __launch_bounds__(256) void k_gemm2(
    const float* __restrict__ Wr2, const float* __restrict__ br2,
    const float* __restrict__ Wm2, const float* __restrict__ bm2,
    const float* __restrict__ theta, const float* __restrict__ log_Pi,
    float* __restrict__ outK, float* __restrict__ outR)
{
    const int n0 = blockIdx.x * 64;   // 0..1023
    const int m0 = blockIdx.y * 64;

    __shared__ float Ars[32][64];
    __shared__ float Ams[32][64];
    __shared__ float Brs[32][64];
    __shared__ float Bms[32][64];

    const int tid = threadIdx.x;
    const int tx = tid & 15;
    const int ty = tid >> 4;

    float accr[4][4], accm[4][4];
    #pragma unroll
    for (int i = 0; i < 4; i++)
        #pragma unroll
        for (int j = 0; j < 4; j++) { accr[i][j] = 0.f; accm[i][j] = 0.f; }

    for (int k0 = 0; k0 < HID_; k0 += 32) {
        // A tiles: 64 rows x 32 cols each -> 512 float4 per tile, 2/thread/tile
        #pragma unroll
        for (int i = 0; i < 2; i++) {
            int f   = tid + i * 256;
            int row = f >> 3;           // m within 64
            int c4  = (f & 7) * 4;      // k within 32
            const float* src = &g_Hbuf[(size_t)(m0 + row) * 256 + k0 + c4];
            float4 vr = *reinterpret_cast<const float4*>(src);
            float4 vm = *reinterpret_cast<const float4*>(src + 128);
            Ars[c4+0][row]=vr.x; Ars[c4+1][row]=vr.y; Ars[c4+2][row]=vr.z; Ars[c4+3][row]=vr.w;
            Ams[c4+0][row]=vm.x; Ams[c4+1][row]=vm.y; Ams[c4+2][row]=vm.z; Ams[c4+3][row]=vm.w;
        }
        // B tiles: 32 rows x 64 cols -> 512 float4 per tile, 2/thread/tile
        #pragma unroll
        for (int i = 0; i < 2; i++) {
            int f   = tid + i * 256;
            int row = f >> 4;           // k within 32
            int c4  = (f & 15) * 4;     // n within 64
            float4 vr = *reinterpret_cast<const float4*>(
                &Wr2[(size_t)(k0 + row) * NS_ + n0 + c4]);
            float4 vm = *reinterpret_cast<const float4*>(
                &Wm2[(size_t)(k0 + row) * NS_ + n0 + c4]);
            *reinterpret_cast<float4*>(&Brs[row][c4]) = vr;
            *reinterpret_cast<float4*>(&Bms[row][c4]) = vm;
        }
        __syncthreads();
        #pragma unroll
        for (int k = 0; k < 32; k++) {
            float4 ar = *reinterpret_cast<const float4*>(&Ars[k][ty * 4]);
            float4 am = *reinterpret_cast<const float4*>(&Ams[k][ty * 4]);
            float4 br = *reinterpret_cast<const float4*>(&Brs[k][tx * 4]);
            float4 bm = *reinterpret_cast<const float4*>(&Bms[k][tx * 4]);
            float arr[4] = {ar.x, ar.y, ar.z, ar.w};
            float amr[4] = {am.x, am.y, am.z, am.w};
            float brr[4] = {br.x, br.y, br.z, br.w};
            float bmr[4] = {bm.x, bm.y, bm.z, bm.w};
            #pragma unroll
            for (int i = 0; i < 4; i++)
                #pragma unroll
                for (int j = 0; j < 4; j++) {
                    accr[i][j] = fmaf(arr[i], brr[j], accr[i][j]);
                    accm[i][j] = fmaf(amr[i], bmr[j], accm[i][j]);
                }
        }
        __syncthreads();
    }

    // Epilogue
    #pragma unroll
    for (int j = 0; j < 4; j++) {
        int c = n0 + tx * 4 + j;
        float br2j = br2[c];
        float bm2j = bm2[c];
        float Piv = expf(log_Pi[c]);
        #pragma unroll
        for (int i = 0; i < 4; i++) {
            int m = m0 + ty * 4 + i;
            size_t idx = (size_t)m * NS_ + c;
            float logR = fminf(fmaxf(accr[i][j] + br2j, -5.0f), 5.0f);
            float R = expf(logR);
            float z = PI_F * tanhf(accm[i][j] + bm2j);
            float diff = z - theta[idx];
            float nu = atan2f(sinf(diff), cosf(diff));
            float Kg = Piv / fmaxf(Piv + R, 1e-8f);
            outR[idx] = R;
            outK[idx] = Kg;
            g_alpha[idx] = 1.0f - Kg;
            g_u[idx] = Kg * nu;
        }
    }
}

// ============================================================================
// Scan pass 1: per (b, c, chunk) aggregate  A = prod(alpha), U = chunk-scan end
// 65536 threads; consecutive threads -> consecutive c => coalesced.
// ============================================================================
__global__ __launch_bounds__(256) void k_scan1()
{
    int g = blockIdx.x * blockDim.x + threadIdx.x;   // 0..65535
    int c     = g & (NS_ - 1);
    int rest  = g >> 10;
    int chunk = rest & (NCH_ - 1);
    int b     = rest >> 4;
    size_t base = ((size_t)(b * L_ + chunk * TCH_)) * NS_ + c;
    float A = 1.0f, U = 0.0f;
    #pragma unroll 8
    for (int j = 0; j < TCH_; j++) {
        float al = g_alpha[base + (size_t)j * NS_];
        float uu = g_u    [base + (size_t)j * NS_];
        A *= al;
        U = fmaf(al, U, uu);
    }
    int sidx = ((b * NS_ + c) * NCH_) + chunk;
    g_cA[sidx] = A;
    g_cU[sidx] = U;
}

// ============================================================================
// Scan pass 2: per channel, sequential scan over 16 chunk aggregates.
// Also emits the tiny Pi output.
// ============================================================================
__global__ __launch_bounds__(256) void k_scan2(const float* __restrict__ log_Pi,
                                               float* __restrict__ outPi)
{
    int ch = blockIdx.x * blockDim.x + threadIdx.x;  // 0..4095
    if (ch < NS_) outPi[ch] = expf(log_Pi[ch]);
    if (ch >= B_ * NS_) return;
    float d = 0.0f;
    int base = ch * NCH_;
    #pragma unroll
    for (int k = 0; k < NCH_; k++) {
        g_carry[base + k] = d;                       // carry INTO chunk k
        d = fmaf(g_cA[base + k], d, g_cU[base + k]);
    }
}

// ============================================================================
// Scan pass 3: re-scan each chunk with its carry, write theta_hat.
// ============================================================================
__global__ __launch_bounds__(256) void k_scan3(const float* __restrict__ theta,
                                               float* __restrict__ outTheta)
{
    int g = blockIdx.x * blockDim.x + threadIdx.x;
    int c     = g & (NS_ - 1);
    int rest  = g >> 10;
    int chunk = rest & (NCH_ - 1);
    int b     = rest >> 4;
    size_t base = ((size_t)(b * L_ + chunk * TCH_)) * NS_ + c;
    float d = g_carry[((b * NS_ + c) * NCH_) + chunk];
    #pragma unroll 8
    for (int j = 0; j < TCH_; j++) {
        size_t idx = base + (size_t)j * NS_;
        float al = g_alpha[idx];
        float uu = g_u[idx];
        d = fmaf(al, d, uu);
        outTheta[idx] = theta[idx] + d;
    }
}

// ============================================================================
// Launch
// Inputs (metadata order): theta_path, content_emb, log_Pi,
//                          Wr1, br1, Wr2, br2, Wm1, bm1, Wm2, bm2
// Output: [theta_hat (16777216), Pi (1024), K (16777216), R (16777216)]
// ============================================================================
extern "C" void kernel_launch(void* const* d_in, const int* in_sizes, int n_in,
                              void* d_out, int out_size)
{
    const float* theta  = (const float*)d_in[0];
    const float* x      = (const float*)d_in[1];
    const float* log_Pi = (const float*)d_in[2];
    const float* Wr1    = (const float*)d_in[3];
    const float* br1    = (const float*)d_in[4];
    const float* Wr2    = (const float*)d_in[5];
    const float* br2    = (const float*)d_in[6];
    const float* Wm1    = (const float*)d_in[7];
    const float* bm1    = (const float*)d_in[8];
    const float* Wm2    = (const float*)d_in[9];
    const float* bm2    = (const float*)d_in[10];

    float* outTheta = (float*)d_out;
    float* outPi    = outTheta + (size_t)M_ * NS_;
    float* outK     = outPi + NS_;
    float* outR     = outK + (size_t)M_ * NS_;

    // GEMM1: grid (256/64, 16384/128)
    dim3 g1(4, 128);
    k_gemm1<<<g1, 256>>>(x, Wr1, br1, Wm1, bm1);

    // GEMM2 + epilogue: grid (1024/64, 16384/64)
    dim3 g2(16, 256);
    k_gemm2<<<g2, 256>>>(Wr2, br2, Wm2, bm2, theta, log_Pi, outK, outR);

    // Scan
    k_scan1<<<(B_ * NS_ * NCH_) / 256, 256>>>();
    k_scan2<<<(B_ * NS_ + 255) / 256, 256>>>(log_Pi, outPi);
    k_scan3<<<(B_ * NS_ * NCH_) / 256, 256>>>(theta, outTheta);
}

// round 2
// speedup vs baseline: 1.0441x; 1.0441x over previous
#include <cuda_runtime.h>
#include <cuda_bf16.h>
#include <math.h>

// Problem dims (fixed by setup_inputs)
#define B_    4
#define L_    4096
#define H_    16
#define NB_   64
#define D_    1024
#define HID_  128
#define NS_   1024            // H_*NB_
#define M_    16384           // B_*L_
#define NCH_  16              // chunks per channel
#define TCH_  256             // timesteps per chunk (NCH_*TCH_ == L_)
#define PI_F  3.14159265358979323846f

// ---------------- scratch (device globals; no allocations allowed) ----------
__device__ float g_Hbuf [M_ * 256];        // gelu(X@W1+b1) for both MLPs, (m, 256)
__device__ float g_alpha[(size_t)M_ * NS_]; // 64 MB
__device__ float g_u    [(size_t)M_ * NS_]; // 64 MB
__device__ float g_cA   [B_ * NS_ * NCH_];
__device__ float g_cU   [B_ * NS_ * NCH_];
__device__ float g_carry[B_ * NS_ * NCH_];

__device__ __forceinline__ float gelu_exact(float v) {
    return 0.5f * v * (1.0f + erff(v * 0.70710678118654752440f));
}

// ============================================================================
// Kernel 1: H = gelu(X @ [Wr1 | Wm1] + [br1 | bm1])
// M=16384, N=256, K=1024.  BM=128, BN=64, BK=16, 256 threads, TM=8, TN=4.
// ============================================================================
__global__ __launch_bounds__(256) void k_gemm1(
    const float* __restrict__ X,
    const float* __restrict__ Wr1, const float* __restrict__ br1,
    const float* __restrict__ Wm1, const float* __restrict__ bm1)
{
    const int bn0 = blockIdx.x * 64;       // 0,64,128,192
    const int bm0 = blockIdx.y * 128;
    const float* W    = (bn0 < 128) ? Wr1 : Wm1;
    const float* bias = (bn0 < 128) ? br1 : bm1;
    const int wcol0 = bn0 & 127;

    __shared__ float As[16][128];
    __shared__ float Bs[16][64];

    const int tid = threadIdx.x;
    const int tx = tid & 15;   // n group (4 cols)
    const int ty = tid >> 4;   // m group (8 rows)

    float acc[8][4];
    #pragma unroll
    for (int i = 0; i < 8; i++)
        #pragma unroll
        for (int j = 0; j < 4; j++) acc[i][j] = 0.f;

    for (int k0 = 0; k0 < D_; k0 += 16) {
        // A tile: 128x16 -> 512 float4, 2 per thread (store transposed)
        #pragma unroll
        for (int i = 0; i < 2; i++) {
            int f   = tid + i * 256;
            int row = f >> 2;
            int c4  = (f & 3) * 4;
            float4 v = *reinterpret_cast<const float4*>(
                &X[(size_t)(bm0 + row) * D_ + k0 + c4]);
            As[c4 + 0][row] = v.x; As[c4 + 1][row] = v.y;
            As[c4 + 2][row] = v.z; As[c4 + 3][row] = v.w;
        }
        // B tile: 16x64 -> 256 float4, 1 per thread
        {
            int row = tid >> 4;
            int c4  = (tid & 15) * 4;
            float4 v = *reinterpret_cast<const float4*>(
                &W[(size_t)(k0 + row) * HID_ + wcol0 + c4]);
            *reinterpret_cast<float4*>(&Bs[row][c4]) = v;
        }
        __syncthreads();
        #pragma unroll
        for (int k = 0; k < 16; k++) {
            float a[8], b[4];
            float4 a0 = *reinterpret_cast<const float4*>(&As[k][ty * 8]);
            float4 a1 = *reinterpret_cast<const float4*>(&As[k][ty * 8 + 4]);
            a[0]=a0.x; a[1]=a0.y; a[2]=a0.z; a[3]=a0.w;
            a[4]=a1.x; a[5]=a1.y; a[6]=a1.z; a[7]=a1.w;
            float4 bb = *reinterpret_cast<const float4*>(&Bs[k][tx * 4]);
            b[0]=bb.x; b[1]=bb.y; b[2]=bb.z; b[3]=bb.w;
            #pragma unroll
            for (int i = 0; i < 8; i++)
                #pragma unroll
                for (int j = 0; j < 4; j++)
                    acc[i][j] = fmaf(a[i], b[j], acc[i][j]);
        }
        __syncthreads();
    }

    #pragma unroll
    for (int j = 0; j < 4; j++) {
        float bj = bias[wcol0 + tx * 4 + j];
        #pragma unroll
        for (int i = 0; i < 8; i++) {
            int m = bm0 + ty * 8 + i;
            float v = acc[i][j] + bj;
            g_Hbuf[(size_t)m * 256 + bn0 + tx * 4 + j] = gelu_exact(v);
        }
    }
}

// ============================================================================
// Kernel 2: both second GEMMs (K=128) + full per-element epilogue.
// BM=64, BN=64, BK=32, 256 threads, TM=4, TN=4, dual accumulators (r & m).
// Writes R, K to d_out regions; alpha,u to scratch.
// ============================================================================
__global__ __launch_bounds__(256) void k_gemm2(
    const float* __restrict__ Wr2, const float* __restrict__ br2,
    const float* __restrict__ Wm2, const float* __restrict__ bm2,
    const float* __restrict__ theta, const float* __restrict__ log_Pi,
    float* __restrict__ outK, float* __restrict__ outR)
{
    const int n0 = blockIdx.x * 64;   // 0..1023
    const int m0 = blockIdx.y * 64;

    __shared__ float Ars[32][64];
    __shared__ float Ams[32][64];
    __shared__ float Brs[32][64];
    __shared__ float Bms[32][64];

    const int tid = threadIdx.x;
    const int tx = tid & 15;
    const int ty = tid >> 4;

    float accr[4][4], accm[4][4];
    #pragma unroll
    for (int i = 0; i < 4; i++)
        #pragma unroll
        for (int j = 0; j < 4; j++) { accr[i][j] = 0.f; accm[i][j] = 0.f; }

    for (int k0 = 0; k0 < HID_; k0 += 32) {
        // A tiles: 64 rows x 32 cols each -> 512 float4 per tile, 2/thread/tile
        #pragma unroll
        for (int i = 0; i < 2; i++) {
            int f   = tid + i * 256;
            int row = f >> 3;           // m within 64
            int c4  = (f & 7) * 4;      // k within 32
            const float* src = &g_Hbuf[(size_t)(m0 + row) * 256 + k0 + c4];
            float4 vr = *reinterpret_cast<const float4*>(src);
            float4 vm = *reinterpret_cast<const float4*>(src + 128);
            Ars[c4+0][row]=vr.x; Ars[c4+1][row]=vr.y; Ars[c4+2][row]=vr.z; Ars[c4+3][row]=vr.w;
            Ams[c4+0][row]=vm.x; Ams[c4+1][row]=vm.y; Ams[c4+2][row]=vm.z; Ams[c4+3][row]=vm.w;
        }
        // B tiles: 32 rows x 64 cols -> 512 float4 per tile, 2/thread/tile
        #pragma unroll
        for (int i = 0; i < 2; i++) {
            int f   = tid + i * 256;
            int row = f >> 4;           // k within 32
            int c4  = (f & 15) * 4;     // n within 64
            float4 vr = *reinterpret_cast<const float4*>(
                &Wr2[(size_t)(k0 + row) * NS_ + n0 + c4]);
            float4 vm = *reinterpret_cast<const float4*>(
                &Wm2[(size_t)(k0 + row) * NS_ + n0 + c4]);
            *reinterpret_cast<float4*>(&Brs[row][c4]) = vr;
            *reinterpret_cast<float4*>(&Bms[row][c4]) = vm;
        }
        __syncthreads();
        #pragma unroll
        for (int k = 0; k < 32; k++) {
            float4 ar = *reinterpret_cast<const float4*>(&Ars[k][ty * 4]);
            float4 am = *reinterpret_cast<const float4*>(&Ams[k][ty * 4]);
            float4 br = *reinterpret_cast<const float4*>(&Brs[k][tx * 4]);
            float4 bm = *reinterpret_cast<const float4*>(&Bms[k][tx * 4]);
            float arr[4] = {ar.x, ar.y, ar.z, ar.w};
            float amr[4] = {am.x, am.y, am.z, am.w};
            float brr[4] = {br.x, br.y, br.z, br.w};
            float bmr[4] = {bm.x, bm.y, bm.z, bm.w};
            #pragma unroll
            for (int i = 0; i < 4; i++)
                #pragma unroll
                for (int j = 0; j < 4; j++) {
                    accr[i][j] = fmaf(arr[i], brr[j], accr[i][j]);
                    accm[i][j] = fmaf(amr[i], bmr[j], accm[i][j]);
                }
        }
        __syncthreads();
    }

    // Epilogue
    #pragma unroll
    for (int j = 0; j < 4; j++) {
        int c = n0 + tx * 4 + j;
        float br2j = br2[c];
        float bm2j = bm2[c];
        float Piv = expf(log_Pi[c]);
        #pragma unroll
        for (int i = 0; i < 4; i++) {
            int m = m0 + ty * 4 + i;
            size_t idx = (size_t)m * NS_ + c;
            float logR = fminf(fmaxf(accr[i][j] + br2j, -5.0f), 5.0f);
            float R = expf(logR);
            float z = PI_F * tanhf(accm[i][j] + bm2j);
            float diff = z - theta[idx];
            float nu = atan2f(sinf(diff), cosf(diff));
            float Kg = Piv / fmaxf(Piv + R, 1e-8f);
            outR[idx] = R;
            outK[idx] = Kg;
            g_alpha[idx] = 1.0f - Kg;
            g_u[idx] = Kg * nu;
        }
    }
}

// ============================================================================
// Scan pass 1: per (b, c, chunk) aggregate  A = prod(alpha), U = chunk-scan end
// 65536 threads; consecutive threads -> consecutive c => coalesced.
// ============================================================================
__global__ __launch_bounds__(256) void k_scan1()
{
    int g = blockIdx.x * blockDim.x + threadIdx.x;   // 0..65535
    int c     = g & (NS_ - 1);
    int rest  = g >> 10;
    int chunk = rest & (NCH_ - 1);
    int b     = rest >> 4;
    size_t base = ((size_t)(b * L_ + chunk * TCH_)) * NS_ + c;
    float A = 1.0f, U = 0.0f;
    #pragma unroll 8
    for (int j = 0; j < TCH_; j++) {
        float al = g_alpha[base + (size_t)j * NS_];
        float uu = g_u    [base + (size_t)j * NS_];
        A *= al;
        U = fmaf(al, U, uu);
    }
    int sidx = ((b * NS_ + c) * NCH_) + chunk;
    g_cA[sidx] = A;
    g_cU[sidx] = U;
}

// ============================================================================
// Scan pass 2: per channel, sequential scan over 16 chunk aggregates.
// Also emits the tiny Pi output.
// ============================================================================
__global__ __launch_bounds__(256) void k_scan2(const float* __restrict__ log_Pi,
                                               float* __restrict__ outPi)
{
    int ch = blockIdx.x * blockDim.x + threadIdx.x;  // 0..4095
    if (ch < NS_) outPi[ch] = expf(log_Pi[ch]);
    if (ch >= B_ * NS_) return;
    float d = 0.0f;
    int base = ch * NCH_;
    #pragma unroll
    for (int k = 0; k < NCH_; k++) {
        g_carry[base + k] = d;                       // carry INTO chunk k
        d = fmaf(g_cA[base + k], d, g_cU[base + k]);
    }
}

// ============================================================================
// Scan pass 3: re-scan each chunk with its carry, write theta_hat.
// ============================================================================
__global__ __launch_bounds__(256) void k_scan3(const float* __restrict__ theta,
                                               float* __restrict__ outTheta)
{
    int g = blockIdx.x * blockDim.x + threadIdx.x;
    int c     = g & (NS_ - 1);
    int rest  = g >> 10;
    int chunk = rest & (NCH_ - 1);
    int b     = rest >> 4;
    size_t base = ((size_t)(b * L_ + chunk * TCH_)) * NS_ + c;
    float d = g_carry[((b * NS_ + c) * NCH_) + chunk];
    #pragma unroll 8
    for (int j = 0; j < TCH_; j++) {
        size_t idx = base + (size_t)j * NS_;
        float al = g_alpha[idx];
        float uu = g_u[idx];
        d = fmaf(al, d, uu);
        outTheta[idx] = theta[idx] + d;
    }
}

// ============================================================================
// Launch
// Inputs (metadata order): theta_path, content_emb, log_Pi,
//                          Wr1, br1, Wr2, br2, Wm1, bm1, Wm2, bm2
// Output: [theta_hat (16777216), Pi (1024), K (16777216), R (16777216)]
// ============================================================================
extern "C" void kernel_launch(void* const* d_in, const int* in_sizes, int n_in,
                              void* d_out, int out_size)
{
    const float* theta  = (const float*)d_in[0];
    const float* x      = (const float*)d_in[1];
    const float* log_Pi = (const float*)d_in[2];
    const float* Wr1    = (const float*)d_in[3];
    const float* br1    = (const float*)d_in[4];
    const float* Wr2    = (const float*)d_in[5];
    const float* br2    = (const float*)d_in[6];
    const float* Wm1    = (const float*)d_in[7];
    const float* bm1    = (const float*)d_in[8];
    const float* Wm2    = (const float*)d_in[9];
    const float* bm2    = (const float*)d_in[10];

    float* outTheta = (float*)d_out;
    float* outPi    = outTheta + (size_t)M_ * NS_;
    float* outK     = outPi + NS_;
    float* outR     = outK + (size_t)M_ * NS_;

    // GEMM1: grid (256/64, 16384/128)
    dim3 g1(4, 128);
    k_gemm1<<<g1, 256>>>(x, Wr1, br1, Wm1, bm1);

    // GEMM2 + epilogue: grid (1024/64, 16384/64)
    dim3 g2(16, 256);
    k_gemm2<<<g2, 256>>>(Wr2, br2, Wm2, bm2, theta, log_Pi, outK, outR);

    // Scan
    k_scan1<<<(B_ * NS_ * NCH_) / 256, 256>>>();
    k_scan2<<<(B_ * NS_ + 255) / 256, 256>>>(log_Pi, outPi);
    k_scan3<<<(B_ * NS_ * NCH_) / 256, 256>>>(theta, outTheta);
}